// round 15
// baseline (speedup 1.0000x reference)
#include <cuda_runtime.h>
#include <cuda_fp16.h>
#include <cstdint>

#define NB 8
#define SS 1024
#define DM 1024
#define HH 16
#define DH 64
#define EXPC 0.045084220027780106f   // 0.03125 * log2(e)

// scratch (device globals: allocation-free)
__device__ __half g_qc[NB*SS*DM];      // fp16 copies of inputs
__device__ __half g_kc[NB*SS*DM];
__device__ __half g_vc[NB*SS*DM];
__device__ __half g_Wqh[DM*DM];
__device__ __half g_Wkh[DM*DM];
__device__ __half g_Wvh[DM*DM];
__device__ __half g_Woh[DM*DM];
__device__ __half g_qh[NB*HH*SS*DH];   // [nh, s, d]  (pre-scaled by EXPC)
__device__ __half g_kh[NB*HH*SS*DH];   // [nh, s, d]
__device__ __half g_vTh[NB*HH*DH*SS];  // [nh, d, s]
__device__ __half g_xhh[NB*SS*HH*DH];  // [n, s, h, d]
__device__ float  g_vsum[NB*HH*DH];    // [nh, d]

// ---------------------------------------------------------------------------
__device__ __forceinline__ uint32_t smem_u32(const void* p) {
    uint32_t a;
    asm("{ .reg .u64 t; cvta.to.shared.u64 t, %1; cvt.u32.u64 %0, t; }"
        : "=r"(a) : "l"(p));
    return a;
}
__device__ __forceinline__ void cpasync16(uint32_t dst, const void* src) {
    asm volatile("cp.async.cg.shared.global [%0], [%1], 16;"
                 :: "r"(dst), "l"(src));
}
#define CP_COMMIT() asm volatile("cp.async.commit_group;" ::: "memory")
#define CP_WAIT2()  asm volatile("cp.async.wait_group 2;" ::: "memory")
#define CP_WAIT1()  asm volatile("cp.async.wait_group 1;" ::: "memory")
#define CP_WAIT0()  asm volatile("cp.async.wait_group 0;" ::: "memory")

__device__ __forceinline__ void ldsm4(uint32_t* r, uint32_t a) {
    asm volatile("ldmatrix.sync.aligned.m8n8.x4.shared.b16 {%0,%1,%2,%3}, [%4];"
                 : "=r"(r[0]), "=r"(r[1]), "=r"(r[2]), "=r"(r[3]) : "r"(a));
}
__device__ __forceinline__ void mmaf16(float* d, const uint32_t* a,
                                       const uint32_t* b) {
    asm volatile("mma.sync.aligned.m16n8k16.row.col.f32.f16.f16.f32 "
                 "{%0,%1,%2,%3}, {%4,%5,%6,%7}, {%8,%9}, {%0,%1,%2,%3};"
                 : "+f"(d[0]), "+f"(d[1]), "+f"(d[2]), "+f"(d[3])
                 : "r"(a[0]), "r"(a[1]), "r"(a[2]), "r"(a[3]),
                   "r"(b[0]), "r"(b[1]));
}
__device__ __forceinline__ uint32_t packh2(float x, float y) {
    __half2 h = __floats2half2_rn(x, y);
    return *reinterpret_cast<uint32_t*>(&h);
}
__device__ __forceinline__ float fexp2(float x) {   // 2^x
    float r;
    asm("ex2.approx.f32 %0, %1;" : "=f"(r) : "f"(x));
    return r;
}

// ---------------------------------------------------------------------------
// f32 -> f16 converter: z=0..2 inputs (8.4M), z=3..6 weights (1M)
// ---------------------------------------------------------------------------
__global__ void __launch_bounds__(256) cvt_kernel(
    const float* q, const float* k, const float* v,
    const float* Wq, const float* Wk, const float* Wv, const float* Wo)
{
    const int z = blockIdx.z;
    const float* src;
    __half* dst;
    int nelem;
    if (z == 0)      { src = q;  dst = g_qc;  nelem = NB * SS * DM; }
    else if (z == 1) { src = k;  dst = g_kc;  nelem = NB * SS * DM; }
    else if (z == 2) { src = v;  dst = g_vc;  nelem = NB * SS * DM; }
    else if (z == 3) { src = Wq; dst = g_Wqh; nelem = DM * DM; }
    else if (z == 4) { src = Wk; dst = g_Wkh; nelem = DM * DM; }
    else if (z == 5) { src = Wv; dst = g_Wvh; nelem = DM * DM; }
    else             { src = Wo; dst = g_Woh; nelem = DM * DM; }
    size_t base = (size_t)blockIdx.x * 2048 + threadIdx.x * 8;
    if (base >= (size_t)nelem) return;
    float4 f0 = reinterpret_cast<const float4*>(src + base)[0];
    float4 f1 = reinterpret_cast<const float4*>(src + base)[1];
    __half2* d2 = reinterpret_cast<__half2*>(dst + base);
    d2[0] = __floats2half2_rn(f0.x, f0.y);
    d2[1] = __floats2half2_rn(f0.z, f0.w);
    d2[2] = __floats2half2_rn(f1.x, f1.y);
    d2[3] = __floats2half2_rn(f1.z, f1.w);
}

// ---------------------------------------------------------------------------
// fp16 GEMM core: acc[4][4][4] = A[bm:,:] * W[bn:,:]^T (128x128x1024)
// 3-stage cp.async pipeline; tiles 128 x 64 halves, smem stride 144B. (R9)
// ---------------------------------------------------------------------------
#define GSTAGE 36864

__device__ __forceinline__ void gemm_core(const __half* __restrict__ Ab,
                                          const __half* __restrict__ Wb,
                                          uint32_t smb, float acc[4][4][4])
{
    const int tid = threadIdx.x, wid = tid >> 5, lane = tid & 31;
    const int wm = wid >> 2, wn = wid & 3;
    const int grp = lane >> 3, lr = lane & 7;
    const uint32_t arow = lr + ((grp & 1) << 3), acb = (grp & 2) << 3;
    const uint32_t brow = lr + ((grp & 2) << 2), bcb = (grp & 1) << 4;
    const int lrow = tid >> 3, lc = tid & 7;

    #pragma unroll
    for (int s = 0; s < 3; s++) {
        #pragma unroll
        for (int i = 0; i < 4; i++) {
            int row = lrow + i * 32;
            cpasync16(smb + s * GSTAGE + row * 144 + lc * 16,
                      Ab + (size_t)row * DM + s * 64 + lc * 8);
            cpasync16(smb + s * GSTAGE + 18432 + row * 144 + lc * 16,
                      Wb + (size_t)row * DM + s * 64 + lc * 8);
        }
        CP_COMMIT();
    }

    int stage = 0;
    for (int kt = 0; kt < 16; kt++) {
        CP_WAIT2();
        __syncthreads();
        const uint32_t sb = smb + stage * GSTAGE;
        #pragma unroll
        for (int kk = 0; kk < 4; kk++) {
            uint32_t af[4][4], bf[2][4];
            #pragma unroll
            for (int mf = 0; mf < 4; mf++)
                ldsm4(af[mf], sb + (wm * 64 + mf * 16 + arow) * 144 + kk * 32 + acb);
            #pragma unroll
            for (int ng = 0; ng < 2; ng++)
                ldsm4(bf[ng], sb + 18432 + (wn * 32 + ng * 16 + brow) * 144 + kk * 32 + bcb);
            #pragma unroll
            for (int mf = 0; mf < 4; mf++)
                #pragma unroll
                for (int nf = 0; nf < 4; nf++)
                    mmaf16(acc[mf][nf], af[mf], (nf & 1) ? bf[nf >> 1] + 2 : bf[nf >> 1]);
        }
        __syncthreads();
        if (kt < 13) {
            #pragma unroll
            for (int i = 0; i < 4; i++) {
                int row = lrow + i * 32;
                cpasync16(smb + stage * GSTAGE + row * 144 + lc * 16,
                          Ab + (size_t)row * DM + (kt + 3) * 64 + lc * 8);
                cpasync16(smb + stage * GSTAGE + 18432 + row * 144 + lc * 16,
                          Wb + (size_t)row * DM + (kt + 3) * 64 + lc * 8);
            }
        }
        CP_COMMIT();
        stage = (stage == 2) ? 0 : stage + 1;
    }
}

// ---------------------------------------------------------------------------
// Merged Q/K/V projections: grid (8, 64, 3). Q output pre-scaled by EXPC.
// ---------------------------------------------------------------------------
__global__ void __launch_bounds__(256, 2) qkv_kernel(
    const float* __restrict__ bq, const float* __restrict__ bk,
    const float* __restrict__ bv)
{
    extern __shared__ char smc[];
    const uint32_t smb = smem_u32(smc);
    const int mode = blockIdx.z;
    const __half* A = (mode == 0) ? g_qc : (mode == 1) ? g_kc : g_vc;
    const __half* W = (mode == 0) ? g_Wqh : (mode == 1) ? g_Wkh : g_Wvh;
    const float* bias = (mode == 0) ? bq : (mode == 1) ? bk : bv;
    const int bn = blockIdx.x * 128, bm = blockIdx.y * 128;

    float acc[4][4][4] = {};
    gemm_core(A + (size_t)bm * DM, W + (size_t)bn * DM, smb, acc);

    const int tid = threadIdx.x, wid = tid >> 5, lane = tid & 31;
    const int g = lane >> 2, t = lane & 3;
    const int wm = wid >> 2, wn = wid & 3;
    const int m0 = bm + wm * 64, n0 = bn + wn * 32;
    const float osc = (mode == 0) ? EXPC : 1.f;
    #pragma unroll
    for (int mf = 0; mf < 4; mf++) {
        int r0 = m0 + mf * 16 + g;
        #pragma unroll
        for (int nf = 0; nf < 4; nf++) {
            int c = n0 + nf * 8 + 2 * t;
            float b0 = bias[c], b1 = bias[c + 1];
            int h = c >> 6, d = c & 63;
            #pragma unroll
            for (int half = 0; half < 2; half++) {
                int r = r0 + half * 8;
                int n = r >> 10, s = r & 1023;
                float v0 = (acc[mf][nf][half * 2 + 0] + b0) * osc;
                float v1 = (acc[mf][nf][half * 2 + 1] + b1) * osc;
                if (mode == 2) {
                    __half* dst = g_vTh + ((size_t)(n * HH + h) * DH + d) * SS + s;
                    dst[0] = __float2half_rn(v0);
                    dst[SS] = __float2half_rn(v1);
                } else {
                    __half* dst = ((mode == 0) ? g_qh : g_kh) +
                                  ((size_t)(n * HH + h) * SS + s) * DH + d;
                    *reinterpret_cast<__half2*>(dst) = __floats2half2_rn(v0, v1);
                }
            }
        }
    }
}

// ---------------------------------------------------------------------------
// Output projection: xout = g_xhh * Wo^T + bo (f32 out, streaming stores)
// ---------------------------------------------------------------------------
__global__ void __launch_bounds__(256, 2) out_kernel(
    const float* __restrict__ bo, float* __restrict__ out)
{
    extern __shared__ char smc[];
    const uint32_t smb = smem_u32(smc);
    const int bn = blockIdx.x * 128, bm = blockIdx.y * 128;

    float acc[4][4][4] = {};
    gemm_core(g_xhh + (size_t)bm * DM, g_Woh + (size_t)bn * DM, smb, acc);

    const int tid = threadIdx.x, wid = tid >> 5, lane = tid & 31;
    const int g = lane >> 2, t = lane & 3;
    const int wm = wid >> 2, wn = wid & 3;
    const int m0 = bm + wm * 64, n0 = bn + wn * 32;
    #pragma unroll
    for (int mf = 0; mf < 4; mf++) {
        int r0 = m0 + mf * 16 + g;
        #pragma unroll
        for (int nf = 0; nf < 4; nf++) {
            int c = n0 + nf * 8 + 2 * t;
            float b0 = bo[c], b1 = bo[c + 1];
            #pragma unroll
            for (int half = 0; half < 2; half++) {
                int r = r0 + half * 8;
                __stcs(reinterpret_cast<float2*>(out + (size_t)r * DM + c),
                       make_float2(acc[mf][nf][half * 2 + 0] + b0,
                                   acc[mf][nf][half * 2 + 1] + b1));
            }
        }
    }
}

// ---------------------------------------------------------------------------
// per-head V column sums (for degenerate all-masked rows)
// ---------------------------------------------------------------------------
__global__ void __launch_bounds__(256) vsum_kernel()
{
    const int nh = blockIdx.x;
    const __half* vb = g_vTh + (size_t)nh * DH * SS;
    const int r = threadIdx.x >> 2, c4 = threadIdx.x & 3;
    float part = 0.f;
    for (int it = 0; it < 32; it++) {
        uint4 u = *reinterpret_cast<const uint4*>(vb + (size_t)r * SS + it * 32 + c4 * 8);
        float2 f0 = __half22float2(*reinterpret_cast<__half2*>(&u.x));
        float2 f1 = __half22float2(*reinterpret_cast<__half2*>(&u.y));
        float2 f2 = __half22float2(*reinterpret_cast<__half2*>(&u.z));
        float2 f3 = __half22float2(*reinterpret_cast<__half2*>(&u.w));
        part += (f0.x + f0.y) + (f1.x + f1.y) + (f2.x + f2.y) + (f3.x + f3.y);
    }
    part += __shfl_xor_sync(0xffffffffu, part, 1);
    part += __shfl_xor_sync(0xffffffffu, part, 2);
    if ((threadIdx.x & 3) == 0) g_vsum[nh * DH + r] = part;
}

// ---------------------------------------------------------------------------
// Fused attention (R11 core). Non-causal w region is zero-filled at kernel
// START (overlaps phase-1 load latency); rare degenerate rows (sum==0) are
// patched to 1/1024 after phase 1. Q pre-scaled by EXPC.
// smem: Q 0..18432, K0 18432.., K1 36864.., V0 55296.., V1 72704..,
//       s_s @90112 (512B), pm @90624 (4KB). total 94720.
// ---------------------------------------------------------------------------
#define AQ 0u
#define AK0 18432u
#define AK1 36864u
#define AV0 55296u
#define AV1 72704u

template<bool DIAG>
__device__ __forceinline__ void p1_tile(
    uint32_t kbase, const uint32_t (&qf)[4][4], const float2* __restrict__ pm2,
    int ktbase, int gq0, int gq1, uint32_t brow, uint32_t bcb, int t,
    float& ts0, float& ts1)
{
    #pragma unroll
    for (int hh = 0; hh < 2; hh++) {
        float acc[8][4] = {};
        #pragma unroll
        for (int kk = 0; kk < 4; kk++) {
            #pragma unroll
            for (int ng = 0; ng < 4; ng++) {
                uint32_t bf[4];
                ldsm4(bf, kbase + (hh * 64 + ng * 16 + brow) * 144 + kk * 32 + bcb);
                mmaf16(acc[ng * 2], qf[kk], bf);
                mmaf16(acc[ng * 2 + 1], qf[kk], bf + 2);
            }
        }
        #pragma unroll
        for (int nf = 0; nf < 8; nf++) {
            int gk = ktbase + hh * 64 + nf * 8 + 2 * t;
            float2 pmv = pm2[gk >> 1];
            float px0 = pmv.x, py0 = pmv.y, px1 = pmv.x, py1 = pmv.y;
            if (DIAG) {
                if (gk > gq0) px0 = 0.f;
                if (gk + 1 > gq0) py0 = 0.f;
                if (gk > gq1) px1 = 0.f;
                if (gk + 1 > gq1) py1 = 0.f;
            }
            ts0 = fmaf(fexp2(acc[nf][0]), px0, ts0);
            ts0 = fmaf(fexp2(acc[nf][1]), py0, ts0);
            ts1 = fmaf(fexp2(acc[nf][2]), px1, ts1);
            ts1 = fmaf(fexp2(acc[nf][3]), py1, ts1);
        }
    }
}

template<bool DIAG>
__device__ __forceinline__ void p2_tile(
    uint32_t kbase, uint32_t vbase, const uint32_t (&qf)[4][4],
    const float2* __restrict__ pm2, int ktbase, int gq0, int gq1,
    uint32_t brow, uint32_t bcb, int t,
    float sc0, float sc1, float ad0, float ad1,
    float* __restrict__ wrow0, float* __restrict__ wrow1, float O[8][4])
{
    #pragma unroll
    for (int hh = 0; hh < 2; hh++) {
        float acc[8][4] = {};
        #pragma unroll
        for (int kk = 0; kk < 4; kk++) {
            #pragma unroll
            for (int ng = 0; ng < 4; ng++) {
                uint32_t bf[4];
                ldsm4(bf, kbase + (hh * 64 + ng * 16 + brow) * 144 + kk * 32 + bcb);
                mmaf16(acc[ng * 2], qf[kk], bf);
                mmaf16(acc[ng * 2 + 1], qf[kk], bf + 2);
            }
        }
        #pragma unroll
        for (int nfp = 0; nfp < 4; nfp++) {
            uint32_t pa[4];
            #pragma unroll
            for (int e = 0; e < 2; e++) {
                int nf = nfp * 2 + e;
                int gk = ktbase + hh * 64 + nf * 8 + 2 * t;
                float2 pmv = pm2[gk >> 1];
                float e0 = fexp2(acc[nf][0]) * pmv.x;
                float e1 = fexp2(acc[nf][1]) * pmv.y;
                float e2 = fexp2(acc[nf][2]) * pmv.x;
                float e3 = fexp2(acc[nf][3]) * pmv.y;
                if (DIAG) {
                    if (gk > gq0) e0 = 0.f;
                    if (gk + 1 > gq0) e1 = 0.f;
                    if (gk > gq1) e2 = 0.f;
                    if (gk + 1 > gq1) e3 = 0.f;
                }
                float p0 = e0 * sc0 + ad0, p1 = e1 * sc0 + ad0;
                float p2 = e2 * sc1 + ad1, p3 = e3 * sc1 + ad1;
                __stcs(reinterpret_cast<float2*>(wrow0 + gk), make_float2(p0, p1));
                __stcs(reinterpret_cast<float2*>(wrow1 + gk), make_float2(p2, p3));
                pa[e * 2 + 0] = packh2(p0, p1);
                pa[e * 2 + 1] = packh2(p2, p3);
            }
            #pragma unroll
            for (int dng = 0; dng < 4; dng++) {
                uint32_t bf[4];
                ldsm4(bf, vbase + (dng * 16 + brow) * 272 + hh * 128 + nfp * 32 + bcb);
                mmaf16(O[dng * 2], pa, bf);
                mmaf16(O[dng * 2 + 1], pa, bf + 2);
            }
        }
    }
}

__global__ void __launch_bounds__(256, 2) attn_kernel(const int* __restrict__ pad,
                                                      float* __restrict__ wout)
{
    extern __shared__ char smc[];
    const uint32_t smb = smem_u32(smc);
    float* s_s = reinterpret_cast<float*>(smc + 90112);
    float* pm = reinterpret_cast<float*>(smc + 90624);
    const float2* pm2 = reinterpret_cast<const float2*>(pm);

    const int tid = threadIdx.x, wid = tid >> 5, lane = tid & 31;
    const int g = lane >> 2, t = lane & 3;
    const int grp = lane >> 3, lr = lane & 7;
    const uint32_t arow = lr + ((grp & 1) << 3), acb = (grp & 2) << 3;
    const uint32_t brow = lr + ((grp & 2) << 2), bcb = (grp & 1) << 4;
    const int nh = blockIdx.x, n = nh >> 4, h = nh & 15;
    const int qt = 7 - blockIdx.y;
    const int q0 = qt * 128;
    const int lrow = tid >> 3, lc = tid & 7;
    const int vrow = tid >> 4, vc = tid & 15;

    const __half* qb = g_qh + ((size_t)nh * SS + q0) * DH;
    const __half* kb = g_kh + (size_t)nh * SS * DH;
    const __half* vb = g_vTh + (size_t)nh * DH * SS;

    for (int i = tid; i < SS; i += 256) pm[i] = pad[n * SS + i] ? 0.f : 1.f;

    // phase-1 prologue: Q + K0 (issued before the fill so loads fly under it)
    #pragma unroll
    for (int i = 0; i < 4; i++) {
        int row = lrow + i * 32;
        cpasync16(smb + AQ + row * 144 + lc * 16, qb + (size_t)row * DH + lc * 8);
        cpasync16(smb + AK0 + row * 144 + lc * 16, kb + (size_t)row * DH + lc * 8);
    }
    CP_COMMIT();

    // early zero-fill of the non-causal region of w (correct for all
    // non-degenerate rows; degenerate rows patched after phase 1)
    const int fs = (qt + 1) * 128;
    if (fs < SS) {
        const float4 z4 = make_float4(0.f, 0.f, 0.f, 0.f);
        for (int r = 0; r < 16; r++) {
            float* wr = wout + ((size_t)nh * SS + q0 + wid * 16 + r) * SS;
            for (int c = fs + lane * 4; c < SS; c += 128)
                __stcs(reinterpret_cast<float4*>(wr + c), z4);
        }
    }

    const int gq0 = q0 + wid * 16 + g;
    const int gq1 = gq0 + 8;
    uint32_t qf[4][4];
    float ts0 = 0.f, ts1 = 0.f;

    // ---------------- phase 1 ----------------
    for (int kt = 0; kt <= qt; kt++) {
        __syncthreads();
        if (kt < qt) {
            uint32_t kd = smb + (((kt + 1) & 1) ? AK1 : AK0);
            #pragma unroll
            for (int i = 0; i < 4; i++) {
                int row = lrow + i * 32;
                cpasync16(kd + row * 144 + lc * 16,
                          kb + (size_t)((kt + 1) * 128 + row) * DH + lc * 8);
            }
        }
        CP_COMMIT();
        CP_WAIT1();
        __syncthreads();
        if (kt == 0) {
            #pragma unroll
            for (int kk = 0; kk < 4; kk++)
                ldsm4(qf[kk], smb + AQ + (wid * 16 + arow) * 144 + kk * 32 + acb);
        }
        uint32_t kbase = smb + ((kt & 1) ? AK1 : AK0);
        if (kt < qt)
            p1_tile<false>(kbase, qf, pm2, kt * 128, gq0, gq1, brow, bcb, t, ts0, ts1);
        else
            p1_tile<true>(kbase, qf, pm2, kt * 128, gq0, gq1, brow, bcb, t, ts0, ts1);
    }

    float s0 = ts0, s1 = ts1;
    s0 += __shfl_xor_sync(0xffffffffu, s0, 1);
    s0 += __shfl_xor_sync(0xffffffffu, s0, 2);
    s1 += __shfl_xor_sync(0xffffffffu, s1, 1);
    s1 += __shfl_xor_sync(0xffffffffu, s1, 2);

    const bool d0 = (s0 == 0.f), d1 = (s1 == 0.f);
    const float inv1024 = 1.f / 1024.f;
    const float sc0 = d0 ? 0.f : 1.f / s0;
    const float sc1 = d1 ? 0.f : 1.f / s1;
    const float ad0 = d0 ? inv1024 : 0.f;
    const float ad1 = d1 ? inv1024 : 0.f;
    if (t == 0) { s_s[wid * 16 + g] = s0; s_s[wid * 16 + g + 8] = s1; }
    __syncthreads();

    // phase-2 prologue: K0 + V0 (overlaps the degenerate patch below)
    #pragma unroll
    for (int i = 0; i < 4; i++) {
        int row = lrow + i * 32;
        cpasync16(smb + AK0 + row * 144 + lc * 16, kb + (size_t)row * DH + lc * 8);
    }
    #pragma unroll
    for (int i = 0; i < 4; i++) {
        int row = vrow + i * 16;
        cpasync16(smb + AV0 + row * 272 + vc * 16, vb + (size_t)row * SS + vc * 8);
    }
    CP_COMMIT();

    // patch rare degenerate rows (all keys masked): non-causal part = 1/1024
    if (fs < SS) {
        for (int r = 0; r < 16; r++) {
            int row = wid * 16 + r;
            if (s_s[row] == 0.f) {
                float4 f4 = make_float4(inv1024, inv1024, inv1024, inv1024);
                float* wr = wout + ((size_t)nh * SS + q0 + row) * SS;
                for (int c = fs + lane * 4; c < SS; c += 128)
                    __stcs(reinterpret_cast<float4*>(wr + c), f4);
            }
        }
    }

    float O[8][4] = {};
    float* wrow0 = wout + ((size_t)nh * SS + gq0) * SS;
    float* wrow1 = wout + ((size_t)nh * SS + gq1) * SS;

    // ---------------- phase 2 ----------------
    for (int kt = 0; kt <= qt; kt++) {
        __syncthreads();
        if (kt < qt) {
            uint32_t kd = smb + (((kt + 1) & 1) ? AK1 : AK0);
            uint32_t vd = smb + (((kt + 1) & 1) ? AV1 : AV0);
            #pragma unroll
            for (int i = 0; i < 4; i++) {
                int row = lrow + i * 32;
                cpasync16(kd + row * 144 + lc * 16,
                          kb + (size_t)((kt + 1) * 128 + row) * DH + lc * 8);
            }
            #pragma unroll
            for (int i = 0; i < 4; i++) {
                int row = vrow + i * 16;
                cpasync16(vd + row * 272 + vc * 16,
                          vb + (size_t)row * SS + (kt + 1) * 128 + vc * 8);
            }
        }
        CP_COMMIT();
        CP_WAIT1();
        __syncthreads();
        uint32_t kbase = smb + ((kt & 1) ? AK1 : AK0);
        uint32_t vbase = smb + ((kt & 1) ? AV1 : AV0);
        if (kt < qt)
            p2_tile<false>(kbase, vbase, qf, pm2, kt * 128, gq0, gq1, brow, bcb, t,
                           sc0, sc1, ad0, ad1, wrow0, wrow1, O);
        else
            p2_tile<true>(kbase, vbase, qf, pm2, kt * 128, gq0, gq1, brow, bcb, t,
                          sc0, sc1, ad0, ad1, wrow0, wrow1, O);
    }

    // ---------------- epilogue: write O (fp16) ----------------
    #pragma unroll
    for (int dn = 0; dn < 8; dn++) {
        int d = dn * 8 + 2 * t;
        float o0 = O[dn][0], o1 = O[dn][1], o2 = O[dn][2], o3 = O[dn][3];
        if (d0) {
            o0 = g_vsum[nh * DH + d] * inv1024;
            o1 = g_vsum[nh * DH + d + 1] * inv1024;
        }
        if (d1) {
            o2 = g_vsum[nh * DH + d] * inv1024;
            o3 = g_vsum[nh * DH + d + 1] * inv1024;
        }
        *reinterpret_cast<__half2*>(
            g_xhh + ((size_t)(n * SS + gq0) * HH + h) * DH + d) = __floats2half2_rn(o0, o1);
        *reinterpret_cast<__half2*>(
            g_xhh + ((size_t)(n * SS + gq1) * HH + h) * DH + d) = __floats2half2_rn(o2, o3);
    }
}

// ---------------------------------------------------------------------------
extern "C" void kernel_launch(void* const* d_in, const int* in_sizes, int n_in,
                              void* d_out, int out_size)
{
    const float* q   = (const float*)d_in[0];
    const float* k   = (const float*)d_in[1];
    const float* v   = (const float*)d_in[2];
    // d_in[3] = causal_mask (computed analytically)
    const int*   pad = (const int*)d_in[4];
    const float* Wq  = (const float*)d_in[5];
    const float* bq  = (const float*)d_in[6];
    const float* Wk  = (const float*)d_in[7];
    const float* bk  = (const float*)d_in[8];
    const float* Wv  = (const float*)d_in[9];
    const float* bv  = (const float*)d_in[10];
    const float* Wo  = (const float*)d_in[11];
    const float* bo  = (const float*)d_in[12];

    float* xout = (float*)d_out;                        // [8,1024,1024]
    float* wout = (float*)d_out + (size_t)NB * SS * DM; // [8,16,1024,1024]

    const int GEMM_SMEM = 3 * GSTAGE;   // 110592
    const int ATTN_SMEM = 94720;
    cudaFuncSetAttribute(qkv_kernel, cudaFuncAttributeMaxDynamicSharedMemorySize, GEMM_SMEM);
    cudaFuncSetAttribute(out_kernel, cudaFuncAttributeMaxDynamicSharedMemorySize, GEMM_SMEM);
    cudaFuncSetAttribute(attn_kernel, cudaFuncAttributeMaxDynamicSharedMemorySize, ATTN_SMEM);

    dim3 cg(4096, 1, 7);
    cvt_kernel<<<cg, 256>>>(q, k, v, Wq, Wk, Wv, Wo);

    dim3 qkvg(DM / 128, (NB * SS) / 128, 3);   // (8, 64, 3)
    qkv_kernel<<<qkvg, 256, GEMM_SMEM>>>(bq, bk, bv);

    vsum_kernel<<<NB * HH, 256>>>();

    dim3 ag(NB * HH, 8);                       // (128 nh, 8 q-tiles)
    attn_kernel<<<ag, 256, ATTN_SMEM>>>(pad, wout);

    dim3 og(DM / 128, (NB * SS) / 128);        // (8, 64)
    out_kernel<<<og, 256, GEMM_SMEM>>>(bo, xout);
}

// round 16
// speedup vs baseline: 1.0098x; 1.0098x over previous
#include <cuda_runtime.h>
#include <cuda_fp16.h>
#include <cstdint>

#define NB 8
#define SS 1024
#define DM 1024
#define HH 16
#define DH 64
#define EXPC 0.045084220027780106f   // 0.03125 * log2(e)

// scratch (device globals: allocation-free)
__device__ __half g_qc[NB*SS*DM];      // fp16 copies of inputs
__device__ __half g_kc[NB*SS*DM];
__device__ __half g_vc[NB*SS*DM];
__device__ __half g_Wqh[DM*DM];
__device__ __half g_Wkh[DM*DM];
__device__ __half g_Wvh[DM*DM];
__device__ __half g_Woh[DM*DM];
__device__ __half g_qh[NB*HH*SS*DH];   // [nh, s, d]  (pre-scaled by EXPC)
__device__ __half g_kh[NB*HH*SS*DH];   // [nh, s, d]
__device__ __half g_vTh[NB*HH*DH*SS];  // [nh, d, s]
__device__ __half g_xhh[NB*SS*HH*DH];  // [n, s, h, d]
__device__ float  g_vsum[NB*HH*DH];    // [nh, d]

// ---------------------------------------------------------------------------
__device__ __forceinline__ uint32_t smem_u32(const void* p) {
    uint32_t a;
    asm("{ .reg .u64 t; cvta.to.shared.u64 t, %1; cvt.u32.u64 %0, t; }"
        : "=r"(a) : "l"(p));
    return a;
}
__device__ __forceinline__ void cpasync16(uint32_t dst, const void* src) {
    asm volatile("cp.async.cg.shared.global [%0], [%1], 16;"
                 :: "r"(dst), "l"(src));
}
#define CP_COMMIT() asm volatile("cp.async.commit_group;" ::: "memory")
#define CP_WAIT2()  asm volatile("cp.async.wait_group 2;" ::: "memory")
#define CP_WAIT1()  asm volatile("cp.async.wait_group 1;" ::: "memory")
#define CP_WAIT0()  asm volatile("cp.async.wait_group 0;" ::: "memory")

__device__ __forceinline__ void ldsm4(uint32_t* r, uint32_t a) {
    asm volatile("ldmatrix.sync.aligned.m8n8.x4.shared.b16 {%0,%1,%2,%3}, [%4];"
                 : "=r"(r[0]), "=r"(r[1]), "=r"(r[2]), "=r"(r[3]) : "r"(a));
}
__device__ __forceinline__ void mmaf16(float* d, const uint32_t* a,
                                       const uint32_t* b) {
    asm volatile("mma.sync.aligned.m16n8k16.row.col.f32.f16.f16.f32 "
                 "{%0,%1,%2,%3}, {%4,%5,%6,%7}, {%8,%9}, {%0,%1,%2,%3};"
                 : "+f"(d[0]), "+f"(d[1]), "+f"(d[2]), "+f"(d[3])
                 : "r"(a[0]), "r"(a[1]), "r"(a[2]), "r"(a[3]),
                   "r"(b[0]), "r"(b[1]));
}
__device__ __forceinline__ uint32_t packh2(float x, float y) {
    __half2 h = __floats2half2_rn(x, y);
    return *reinterpret_cast<uint32_t*>(&h);
}
__device__ __forceinline__ float fexp2(float x) {   // 2^x
    float r;
    asm("ex2.approx.f32 %0, %1;" : "=f"(r) : "f"(x));
    return r;
}

// ---------------------------------------------------------------------------
// f32 -> f16 converter: z=0..2 inputs (8.4M), z=3..6 weights (1M)
// Streaming stores: outputs exceed L2; keep weight/pad lines resident.
// ---------------------------------------------------------------------------
__global__ void __launch_bounds__(256) cvt_kernel(
    const float* q, const float* k, const float* v,
    const float* Wq, const float* Wk, const float* Wv, const float* Wo)
{
    const int z = blockIdx.z;
    const float* src;
    __half* dst;
    int nelem;
    if (z == 0)      { src = q;  dst = g_qc;  nelem = NB * SS * DM; }
    else if (z == 1) { src = k;  dst = g_kc;  nelem = NB * SS * DM; }
    else if (z == 2) { src = v;  dst = g_vc;  nelem = NB * SS * DM; }
    else if (z == 3) { src = Wq; dst = g_Wqh; nelem = DM * DM; }
    else if (z == 4) { src = Wk; dst = g_Wkh; nelem = DM * DM; }
    else if (z == 5) { src = Wv; dst = g_Wvh; nelem = DM * DM; }
    else             { src = Wo; dst = g_Woh; nelem = DM * DM; }
    size_t base = (size_t)blockIdx.x * 2048 + threadIdx.x * 8;
    if (base >= (size_t)nelem) return;
    float4 f0 = reinterpret_cast<const float4*>(src + base)[0];
    float4 f1 = reinterpret_cast<const float4*>(src + base)[1];
    uint4 u;
    u.x = packh2(f0.x, f0.y);
    u.y = packh2(f0.z, f0.w);
    u.z = packh2(f1.x, f1.y);
    u.w = packh2(f1.z, f1.w);
    __stcs(reinterpret_cast<uint4*>(dst + base), u);
}

// ---------------------------------------------------------------------------
// fp16 GEMM core: acc[4][4][4] = A[bm:,:] * W[bn:,:]^T (128x128x1024)
// 3-stage cp.async pipeline; tiles 128 x 64 halves, smem stride 144B. (R9)
// ---------------------------------------------------------------------------
#define GSTAGE 36864

__device__ __forceinline__ void gemm_core(const __half* __restrict__ Ab,
                                          const __half* __restrict__ Wb,
                                          uint32_t smb, float acc[4][4][4])
{
    const int tid = threadIdx.x, wid = tid >> 5, lane = tid & 31;
    const int wm = wid >> 2, wn = wid & 3;
    const int grp = lane >> 3, lr = lane & 7;
    const uint32_t arow = lr + ((grp & 1) << 3), acb = (grp & 2) << 3;
    const uint32_t brow = lr + ((grp & 2) << 2), bcb = (grp & 1) << 4;
    const int lrow = tid >> 3, lc = tid & 7;

    #pragma unroll
    for (int s = 0; s < 3; s++) {
        #pragma unroll
        for (int i = 0; i < 4; i++) {
            int row = lrow + i * 32;
            cpasync16(smb + s * GSTAGE + row * 144 + lc * 16,
                      Ab + (size_t)row * DM + s * 64 + lc * 8);
            cpasync16(smb + s * GSTAGE + 18432 + row * 144 + lc * 16,
                      Wb + (size_t)row * DM + s * 64 + lc * 8);
        }
        CP_COMMIT();
    }

    int stage = 0;
    for (int kt = 0; kt < 16; kt++) {
        CP_WAIT2();
        __syncthreads();
        const uint32_t sb = smb + stage * GSTAGE;
        #pragma unroll
        for (int kk = 0; kk < 4; kk++) {
            uint32_t af[4][4], bf[2][4];
            #pragma unroll
            for (int mf = 0; mf < 4; mf++)
                ldsm4(af[mf], sb + (wm * 64 + mf * 16 + arow) * 144 + kk * 32 + acb);
            #pragma unroll
            for (int ng = 0; ng < 2; ng++)
                ldsm4(bf[ng], sb + 18432 + (wn * 32 + ng * 16 + brow) * 144 + kk * 32 + bcb);
            #pragma unroll
            for (int mf = 0; mf < 4; mf++)
                #pragma unroll
                for (int nf = 0; nf < 4; nf++)
                    mmaf16(acc[mf][nf], af[mf], (nf & 1) ? bf[nf >> 1] + 2 : bf[nf >> 1]);
        }
        __syncthreads();
        if (kt < 13) {
            #pragma unroll
            for (int i = 0; i < 4; i++) {
                int row = lrow + i * 32;
                cpasync16(smb + stage * GSTAGE + row * 144 + lc * 16,
                          Ab + (size_t)row * DM + (kt + 3) * 64 + lc * 8);
                cpasync16(smb + stage * GSTAGE + 18432 + row * 144 + lc * 16,
                          Wb + (size_t)row * DM + (kt + 3) * 64 + lc * 8);
            }
        }
        CP_COMMIT();
        stage = (stage == 2) ? 0 : stage + 1;
    }
}

// ---------------------------------------------------------------------------
// Merged Q/K/V projections: grid (8, 64, 3). Q output pre-scaled by EXPC.
// ---------------------------------------------------------------------------
__global__ void __launch_bounds__(256, 2) qkv_kernel(
    const float* __restrict__ bq, const float* __restrict__ bk,
    const float* __restrict__ bv)
{
    extern __shared__ char smc[];
    const uint32_t smb = smem_u32(smc);
    const int mode = blockIdx.z;
    const __half* A = (mode == 0) ? g_qc : (mode == 1) ? g_kc : g_vc;
    const __half* W = (mode == 0) ? g_Wqh : (mode == 1) ? g_Wkh : g_Wvh;
    const float* bias = (mode == 0) ? bq : (mode == 1) ? bk : bv;
    const int bn = blockIdx.x * 128, bm = blockIdx.y * 128;

    float acc[4][4][4] = {};
    gemm_core(A + (size_t)bm * DM, W + (size_t)bn * DM, smb, acc);

    const int tid = threadIdx.x, wid = tid >> 5, lane = tid & 31;
    const int g = lane >> 2, t = lane & 3;
    const int wm = wid >> 2, wn = wid & 3;
    const int m0 = bm + wm * 64, n0 = bn + wn * 32;
    const float osc = (mode == 0) ? EXPC : 1.f;
    #pragma unroll
    for (int mf = 0; mf < 4; mf++) {
        int r0 = m0 + mf * 16 + g;
        #pragma unroll
        for (int nf = 0; nf < 4; nf++) {
            int c = n0 + nf * 8 + 2 * t;
            float b0 = bias[c], b1 = bias[c + 1];
            int h = c >> 6, d = c & 63;
            #pragma unroll
            for (int half = 0; half < 2; half++) {
                int r = r0 + half * 8;
                int n = r >> 10, s = r & 1023;
                float v0 = (acc[mf][nf][half * 2 + 0] + b0) * osc;
                float v1 = (acc[mf][nf][half * 2 + 1] + b1) * osc;
                if (mode == 2) {
                    __half* dst = g_vTh + ((size_t)(n * HH + h) * DH + d) * SS + s;
                    dst[0] = __float2half_rn(v0);
                    dst[SS] = __float2half_rn(v1);
                } else {
                    __half* dst = ((mode == 0) ? g_qh : g_kh) +
                                  ((size_t)(n * HH + h) * SS + s) * DH + d;
                    *reinterpret_cast<__half2*>(dst) = __floats2half2_rn(v0, v1);
                }
            }
        }
    }
}

// ---------------------------------------------------------------------------
// Output projection: xout = g_xhh * Wo^T + bo (f32 out, streaming stores)
// ---------------------------------------------------------------------------
__global__ void __launch_bounds__(256, 2) out_kernel(
    const float* __restrict__ bo, float* __restrict__ out)
{
    extern __shared__ char smc[];
    const uint32_t smb = smem_u32(smc);
    const int bn = blockIdx.x * 128, bm = blockIdx.y * 128;

    float acc[4][4][4] = {};
    gemm_core(g_xhh + (size_t)bm * DM, g_Woh + (size_t)bn * DM, smb, acc);

    const int tid = threadIdx.x, wid = tid >> 5, lane = tid & 31;
    const int g = lane >> 2, t = lane & 3;
    const int wm = wid >> 2, wn = wid & 3;
    const int m0 = bm + wm * 64, n0 = bn + wn * 32;
    #pragma unroll
    for (int mf = 0; mf < 4; mf++) {
        int r0 = m0 + mf * 16 + g;
        #pragma unroll
        for (int nf = 0; nf < 4; nf++) {
            int c = n0 + nf * 8 + 2 * t;
            float b0 = bo[c], b1 = bo[c + 1];
            #pragma unroll
            for (int half = 0; half < 2; half++) {
                int r = r0 + half * 8;
                __stcs(reinterpret_cast<float2*>(out + (size_t)r * DM + c),
                       make_float2(acc[mf][nf][half * 2 + 0] + b0,
                                   acc[mf][nf][half * 2 + 1] + b1));
            }
        }
    }
}

// ---------------------------------------------------------------------------
// per-head V column sums (for degenerate all-masked rows)
// ---------------------------------------------------------------------------
__global__ void __launch_bounds__(256) vsum_kernel()
{
    const int nh = blockIdx.x;
    const __half* vb = g_vTh + (size_t)nh * DH * SS;
    const int r = threadIdx.x >> 2, c4 = threadIdx.x & 3;
    float part = 0.f;
    for (int it = 0; it < 32; it++) {
        uint4 u = *reinterpret_cast<const uint4*>(vb + (size_t)r * SS + it * 32 + c4 * 8);
        float2 f0 = __half22float2(*reinterpret_cast<__half2*>(&u.x));
        float2 f1 = __half22float2(*reinterpret_cast<__half2*>(&u.y));
        float2 f2 = __half22float2(*reinterpret_cast<__half2*>(&u.z));
        float2 f3 = __half22float2(*reinterpret_cast<__half2*>(&u.w));
        part += (f0.x + f0.y) + (f1.x + f1.y) + (f2.x + f2.y) + (f3.x + f3.y);
    }
    part += __shfl_xor_sync(0xffffffffu, part, 1);
    part += __shfl_xor_sync(0xffffffffu, part, 2);
    if ((threadIdx.x & 3) == 0) g_vsum[nh * DH + r] = part;
}

// ---------------------------------------------------------------------------
// Fused attention (R11 proven-best). Q pre-scaled by EXPC.
// smem: Q 0..18432, K0 18432.., K1 36864.., V0 55296.., V1 72704..,
//       s_s @90112 (512B), pm @90624 (4KB). total 94720.
// ---------------------------------------------------------------------------
#define AQ 0u
#define AK0 18432u
#define AK1 36864u
#define AV0 55296u
#define AV1 72704u

template<bool DIAG>
__device__ __forceinline__ void p1_tile(
    uint32_t kbase, const uint32_t (&qf)[4][4], const float2* __restrict__ pm2,
    int ktbase, int gq0, int gq1, uint32_t brow, uint32_t bcb, int t,
    float& ts0, float& ts1)
{
    #pragma unroll
    for (int hh = 0; hh < 2; hh++) {
        float acc[8][4] = {};
        #pragma unroll
        for (int kk = 0; kk < 4; kk++) {
            #pragma unroll
            for (int ng = 0; ng < 4; ng++) {
                uint32_t bf[4];
                ldsm4(bf, kbase + (hh * 64 + ng * 16 + brow) * 144 + kk * 32 + bcb);
                mmaf16(acc[ng * 2], qf[kk], bf);
                mmaf16(acc[ng * 2 + 1], qf[kk], bf + 2);
            }
        }
        #pragma unroll
        for (int nf = 0; nf < 8; nf++) {
            int gk = ktbase + hh * 64 + nf * 8 + 2 * t;
            float2 pmv = pm2[gk >> 1];
            float px0 = pmv.x, py0 = pmv.y, px1 = pmv.x, py1 = pmv.y;
            if (DIAG) {
                if (gk > gq0) px0 = 0.f;
                if (gk + 1 > gq0) py0 = 0.f;
                if (gk > gq1) px1 = 0.f;
                if (gk + 1 > gq1) py1 = 0.f;
            }
            ts0 = fmaf(fexp2(acc[nf][0]), px0, ts0);
            ts0 = fmaf(fexp2(acc[nf][1]), py0, ts0);
            ts1 = fmaf(fexp2(acc[nf][2]), px1, ts1);
            ts1 = fmaf(fexp2(acc[nf][3]), py1, ts1);
        }
    }
}

template<bool DIAG>
__device__ __forceinline__ void p2_tile(
    uint32_t kbase, uint32_t vbase, const uint32_t (&qf)[4][4],
    const float2* __restrict__ pm2, int ktbase, int gq0, int gq1,
    uint32_t brow, uint32_t bcb, int t,
    float sc0, float sc1, float ad0, float ad1,
    float* __restrict__ wrow0, float* __restrict__ wrow1, float O[8][4])
{
    #pragma unroll
    for (int hh = 0; hh < 2; hh++) {
        float acc[8][4] = {};
        #pragma unroll
        for (int kk = 0; kk < 4; kk++) {
            #pragma unroll
            for (int ng = 0; ng < 4; ng++) {
                uint32_t bf[4];
                ldsm4(bf, kbase + (hh * 64 + ng * 16 + brow) * 144 + kk * 32 + bcb);
                mmaf16(acc[ng * 2], qf[kk], bf);
                mmaf16(acc[ng * 2 + 1], qf[kk], bf + 2);
            }
        }
        #pragma unroll
        for (int nfp = 0; nfp < 4; nfp++) {
            uint32_t pa[4];
            #pragma unroll
            for (int e = 0; e < 2; e++) {
                int nf = nfp * 2 + e;
                int gk = ktbase + hh * 64 + nf * 8 + 2 * t;
                float2 pmv = pm2[gk >> 1];
                float e0 = fexp2(acc[nf][0]) * pmv.x;
                float e1 = fexp2(acc[nf][1]) * pmv.y;
                float e2 = fexp2(acc[nf][2]) * pmv.x;
                float e3 = fexp2(acc[nf][3]) * pmv.y;
                if (DIAG) {
                    if (gk > gq0) e0 = 0.f;
                    if (gk + 1 > gq0) e1 = 0.f;
                    if (gk > gq1) e2 = 0.f;
                    if (gk + 1 > gq1) e3 = 0.f;
                }
                float p0 = e0 * sc0 + ad0, p1 = e1 * sc0 + ad0;
                float p2 = e2 * sc1 + ad1, p3 = e3 * sc1 + ad1;
                __stcs(reinterpret_cast<float2*>(wrow0 + gk), make_float2(p0, p1));
                __stcs(reinterpret_cast<float2*>(wrow1 + gk), make_float2(p2, p3));
                pa[e * 2 + 0] = packh2(p0, p1);
                pa[e * 2 + 1] = packh2(p2, p3);
            }
            #pragma unroll
            for (int dng = 0; dng < 4; dng++) {
                uint32_t bf[4];
                ldsm4(bf, vbase + (dng * 16 + brow) * 272 + hh * 128 + nfp * 32 + bcb);
                mmaf16(O[dng * 2], pa, bf);
                mmaf16(O[dng * 2 + 1], pa, bf + 2);
            }
        }
    }
}

__global__ void __launch_bounds__(256, 2) attn_kernel(const int* __restrict__ pad,
                                                      float* __restrict__ wout)
{
    extern __shared__ char smc[];
    const uint32_t smb = smem_u32(smc);
    float* s_s = reinterpret_cast<float*>(smc + 90112);
    float* pm = reinterpret_cast<float*>(smc + 90624);
    const float2* pm2 = reinterpret_cast<const float2*>(pm);

    const int tid = threadIdx.x, wid = tid >> 5, lane = tid & 31;
    const int g = lane >> 2, t = lane & 3;
    const int grp = lane >> 3, lr = lane & 7;
    const uint32_t arow = lr + ((grp & 1) << 3), acb = (grp & 2) << 3;
    const uint32_t brow = lr + ((grp & 2) << 2), bcb = (grp & 1) << 4;
    const int nh = blockIdx.x, n = nh >> 4, h = nh & 15;
    const int qt = 7 - blockIdx.y;
    const int q0 = qt * 128;
    const int lrow = tid >> 3, lc = tid & 7;
    const int vrow = tid >> 4, vc = tid & 15;

    const __half* qb = g_qh + ((size_t)nh * SS + q0) * DH;
    const __half* kb = g_kh + (size_t)nh * SS * DH;
    const __half* vb = g_vTh + (size_t)nh * DH * SS;

    for (int i = tid; i < SS; i += 256) pm[i] = pad[n * SS + i] ? 0.f : 1.f;

    #pragma unroll
    for (int i = 0; i < 4; i++) {
        int row = lrow + i * 32;
        cpasync16(smb + AQ + row * 144 + lc * 16, qb + (size_t)row * DH + lc * 8);
        cpasync16(smb + AK0 + row * 144 + lc * 16, kb + (size_t)row * DH + lc * 8);
    }
    CP_COMMIT();

    const int gq0 = q0 + wid * 16 + g;
    const int gq1 = gq0 + 8;
    uint32_t qf[4][4];
    float ts0 = 0.f, ts1 = 0.f;

    // ---------------- phase 1 ----------------
    for (int kt = 0; kt <= qt; kt++) {
        __syncthreads();
        if (kt < qt) {
            uint32_t kd = smb + (((kt + 1) & 1) ? AK1 : AK0);
            #pragma unroll
            for (int i = 0; i < 4; i++) {
                int row = lrow + i * 32;
                cpasync16(kd + row * 144 + lc * 16,
                          kb + (size_t)((kt + 1) * 128 + row) * DH + lc * 8);
            }
        }
        CP_COMMIT();
        CP_WAIT1();
        __syncthreads();
        if (kt == 0) {
            #pragma unroll
            for (int kk = 0; kk < 4; kk++)
                ldsm4(qf[kk], smb + AQ + (wid * 16 + arow) * 144 + kk * 32 + acb);
        }
        uint32_t kbase = smb + ((kt & 1) ? AK1 : AK0);
        if (kt < qt)
            p1_tile<false>(kbase, qf, pm2, kt * 128, gq0, gq1, brow, bcb, t, ts0, ts1);
        else
            p1_tile<true>(kbase, qf, pm2, kt * 128, gq0, gq1, brow, bcb, t, ts0, ts1);
    }

    float s0 = ts0, s1 = ts1;
    s0 += __shfl_xor_sync(0xffffffffu, s0, 1);
    s0 += __shfl_xor_sync(0xffffffffu, s0, 2);
    s1 += __shfl_xor_sync(0xffffffffu, s1, 1);
    s1 += __shfl_xor_sync(0xffffffffu, s1, 2);

    const bool d0 = (s0 == 0.f), d1 = (s1 == 0.f);
    const float inv1024 = 1.f / 1024.f;
    const float sc0 = d0 ? 0.f : 1.f / s0;
    const float sc1 = d1 ? 0.f : 1.f / s1;
    const float ad0 = d0 ? inv1024 : 0.f;
    const float ad1 = d1 ? inv1024 : 0.f;
    if (t == 0) { s_s[wid * 16 + g] = s0; s_s[wid * 16 + g + 8] = s1; }
    __syncthreads();

    // phase-2 prologue: K0 + V0 (overlaps the w-fill below)
    #pragma unroll
    for (int i = 0; i < 4; i++) {
        int row = lrow + i * 32;
        cpasync16(smb + AK0 + row * 144 + lc * 16, kb + (size_t)row * DH + lc * 8);
    }
    #pragma unroll
    for (int i = 0; i < 4; i++) {
        int row = vrow + i * 16;
        cpasync16(smb + AV0 + row * 272 + vc * 16, vb + (size_t)row * SS + vc * 8);
    }
    CP_COMMIT();

    // fill non-causal region of w
    const int fs = (qt + 1) * 128;
    if (fs < SS) {
        for (int r = 0; r < 16; r++) {
            int row = wid * 16 + r;
            float val = (s_s[row] == 0.f) ? inv1024 : 0.f;
            float4 f4 = make_float4(val, val, val, val);
            float* wr = wout + ((size_t)nh * SS + q0 + row) * SS;
            for (int c = fs + lane * 4; c < SS; c += 128)
                __stcs(reinterpret_cast<float4*>(wr + c), f4);
        }
    }

    float O[8][4] = {};
    float* wrow0 = wout + ((size_t)nh * SS + gq0) * SS;
    float* wrow1 = wout + ((size_t)nh * SS + gq1) * SS;

    // ---------------- phase 2 ----------------
    for (int kt = 0; kt <= qt; kt++) {
        __syncthreads();
        if (kt < qt) {
            uint32_t kd = smb + (((kt + 1) & 1) ? AK1 : AK0);
            uint32_t vd = smb + (((kt + 1) & 1) ? AV1 : AV0);
            #pragma unroll
            for (int i = 0; i < 4; i++) {
                int row = lrow + i * 32;
                cpasync16(kd + row * 144 + lc * 16,
                          kb + (size_t)((kt + 1) * 128 + row) * DH + lc * 8);
            }
            #pragma unroll
            for (int i = 0; i < 4; i++) {
                int row = vrow + i * 16;
                cpasync16(vd + row * 272 + vc * 16,
                          vb + (size_t)row * SS + (kt + 1) * 128 + vc * 8);
            }
        }
        CP_COMMIT();
        CP_WAIT1();
        __syncthreads();
        uint32_t kbase = smb + ((kt & 1) ? AK1 : AK0);
        uint32_t vbase = smb + ((kt & 1) ? AV1 : AV0);
        if (kt < qt)
            p2_tile<false>(kbase, vbase, qf, pm2, kt * 128, gq0, gq1, brow, bcb, t,
                           sc0, sc1, ad0, ad1, wrow0, wrow1, O);
        else
            p2_tile<true>(kbase, vbase, qf, pm2, kt * 128, gq0, gq1, brow, bcb, t,
                          sc0, sc1, ad0, ad1, wrow0, wrow1, O);
    }

    // ---------------- epilogue: write O (fp16) ----------------
    #pragma unroll
    for (int dn = 0; dn < 8; dn++) {
        int d = dn * 8 + 2 * t;
        float o0 = O[dn][0], o1 = O[dn][1], o2 = O[dn][2], o3 = O[dn][3];
        if (d0) {
            o0 = g_vsum[nh * DH + d] * inv1024;
            o1 = g_vsum[nh * DH + d + 1] * inv1024;
        }
        if (d1) {
            o2 = g_vsum[nh * DH + d] * inv1024;
            o3 = g_vsum[nh * DH + d + 1] * inv1024;
        }
        *reinterpret_cast<__half2*>(
            g_xhh + ((size_t)(n * SS + gq0) * HH + h) * DH + d) = __floats2half2_rn(o0, o1);
        *reinterpret_cast<__half2*>(
            g_xhh + ((size_t)(n * SS + gq1) * HH + h) * DH + d) = __floats2half2_rn(o2, o3);
    }
}

// ---------------------------------------------------------------------------
extern "C" void kernel_launch(void* const* d_in, const int* in_sizes, int n_in,
                              void* d_out, int out_size)
{
    const float* q   = (const float*)d_in[0];
    const float* k   = (const float*)d_in[1];
    const float* v   = (const float*)d_in[2];
    // d_in[3] = causal_mask (computed analytically)
    const int*   pad = (const int*)d_in[4];
    const float* Wq  = (const float*)d_in[5];
    const float* bq  = (const float*)d_in[6];
    const float* Wk  = (const float*)d_in[7];
    const float* bk  = (const float*)d_in[8];
    const float* Wv  = (const float*)d_in[9];
    const float* bv  = (const float*)d_in[10];
    const float* Wo  = (const float*)d_in[11];
    const float* bo  = (const float*)d_in[12];

    float* xout = (float*)d_out;                        // [8,1024,1024]
    float* wout = (float*)d_out + (size_t)NB * SS * DM; // [8,16,1024,1024]

    const int GEMM_SMEM = 3 * GSTAGE;   // 110592
    const int ATTN_SMEM = 94720;
    cudaFuncSetAttribute(qkv_kernel, cudaFuncAttributeMaxDynamicSharedMemorySize, GEMM_SMEM);
    cudaFuncSetAttribute(out_kernel, cudaFuncAttributeMaxDynamicSharedMemorySize, GEMM_SMEM);
    cudaFuncSetAttribute(attn_kernel, cudaFuncAttributeMaxDynamicSharedMemorySize, ATTN_SMEM);

    dim3 cg(4096, 1, 7);
    cvt_kernel<<<cg, 256>>>(q, k, v, Wq, Wk, Wv, Wo);

    dim3 qkvg(DM / 128, (NB * SS) / 128, 3);   // (8, 64, 3)
    qkv_kernel<<<qkvg, 256, GEMM_SMEM>>>(bq, bk, bv);

    vsum_kernel<<<NB * HH, 256>>>();

    dim3 ag(NB * HH, 8);                       // (128 nh, 8 q-tiles)
    attn_kernel<<<ag, 256, ATTN_SMEM>>>(pad, wout);

    dim3 og(DM / 128, (NB * SS) / 128);        // (8, 64)
    out_kernel<<<og, 256, GEMM_SMEM>>>(bo, xout);
}

// round 17
// speedup vs baseline: 1.0197x; 1.0098x over previous
#include <cuda_runtime.h>
#include <cuda_fp16.h>
#include <cstdint>

#define NB 8
#define SS 1024
#define DM 1024
#define HH 16
#define DH 64
#define EXPC 0.045084220027780106f   // 0.03125 * log2(e)

// scratch (device globals: allocation-free)
__device__ __half g_qc[NB*SS*DM];      // fp16 copies of inputs
__device__ __half g_kc[NB*SS*DM];
__device__ __half g_vc[NB*SS*DM];
__device__ __half g_Wqh[DM*DM];
__device__ __half g_Wkh[DM*DM];
__device__ __half g_Wvh[DM*DM];
__device__ __half g_Woh[DM*DM];
__device__ __half g_qh[NB*HH*SS*DH];   // [nh, s, d]  (pre-scaled by EXPC)
__device__ __half g_kh[NB*HH*SS*DH];   // [nh, s, d]
__device__ __half g_vTh[NB*HH*DH*SS];  // [nh, d, s]
__device__ __half g_xhh[NB*SS*HH*DH];  // [n, s, h, d]
__device__ float  g_vsum[NB*HH*DH];    // [nh, d] (zeroed in cvt, red-add in qkv)

// ---------------------------------------------------------------------------
__device__ __forceinline__ uint32_t smem_u32(const void* p) {
    uint32_t a;
    asm("{ .reg .u64 t; cvta.to.shared.u64 t, %1; cvt.u32.u64 %0, t; }"
        : "=r"(a) : "l"(p));
    return a;
}
__device__ __forceinline__ void cpasync16(uint32_t dst, const void* src) {
    asm volatile("cp.async.cg.shared.global [%0], [%1], 16;"
                 :: "r"(dst), "l"(src));
}
#define CP_COMMIT() asm volatile("cp.async.commit_group;" ::: "memory")
#define CP_WAIT2()  asm volatile("cp.async.wait_group 2;" ::: "memory")
#define CP_WAIT1()  asm volatile("cp.async.wait_group 1;" ::: "memory")
#define CP_WAIT0()  asm volatile("cp.async.wait_group 0;" ::: "memory")

__device__ __forceinline__ void ldsm4(uint32_t* r, uint32_t a) {
    asm volatile("ldmatrix.sync.aligned.m8n8.x4.shared.b16 {%0,%1,%2,%3}, [%4];"
                 : "=r"(r[0]), "=r"(r[1]), "=r"(r[2]), "=r"(r[3]) : "r"(a));
}
__device__ __forceinline__ void mmaf16(float* d, const uint32_t* a,
                                       const uint32_t* b) {
    asm volatile("mma.sync.aligned.m16n8k16.row.col.f32.f16.f16.f32 "
                 "{%0,%1,%2,%3}, {%4,%5,%6,%7}, {%8,%9}, {%0,%1,%2,%3};"
                 : "+f"(d[0]), "+f"(d[1]), "+f"(d[2]), "+f"(d[3])
                 : "r"(a[0]), "r"(a[1]), "r"(a[2]), "r"(a[3]),
                   "r"(b[0]), "r"(b[1]));
}
__device__ __forceinline__ uint32_t packh2(float x, float y) {
    __half2 h = __floats2half2_rn(x, y);
    return *reinterpret_cast<uint32_t*>(&h);
}
__device__ __forceinline__ float fexp2(float x) {   // 2^x
    float r;
    asm("ex2.approx.f32 %0, %1;" : "=f"(r) : "f"(x));
    return r;
}

// ---------------------------------------------------------------------------
// f32 -> f16 converter: z=0..2 inputs (8.4M), z=3..6 weights (1M).
// z==6 blocks 0..3 also zero g_vsum (accumulated by qkv via red-adds).
// ---------------------------------------------------------------------------
__global__ void __launch_bounds__(256) cvt_kernel(
    const float* q, const float* k, const float* v,
    const float* Wq, const float* Wk, const float* Wv, const float* Wo)
{
    const int z = blockIdx.z;
    if (z == 6 && blockIdx.x < 4) {
        float4 z4 = make_float4(0.f, 0.f, 0.f, 0.f);
        float* p = g_vsum + blockIdx.x * 2048 + threadIdx.x * 8;
        reinterpret_cast<float4*>(p)[0] = z4;
        reinterpret_cast<float4*>(p)[1] = z4;
    }
    const float* src;
    __half* dst;
    int nelem;
    if (z == 0)      { src = q;  dst = g_qc;  nelem = NB * SS * DM; }
    else if (z == 1) { src = k;  dst = g_kc;  nelem = NB * SS * DM; }
    else if (z == 2) { src = v;  dst = g_vc;  nelem = NB * SS * DM; }
    else if (z == 3) { src = Wq; dst = g_Wqh; nelem = DM * DM; }
    else if (z == 4) { src = Wk; dst = g_Wkh; nelem = DM * DM; }
    else if (z == 5) { src = Wv; dst = g_Wvh; nelem = DM * DM; }
    else             { src = Wo; dst = g_Woh; nelem = DM * DM; }
    size_t base = (size_t)blockIdx.x * 2048 + threadIdx.x * 8;
    if (base >= (size_t)nelem) return;
    float4 f0 = reinterpret_cast<const float4*>(src + base)[0];
    float4 f1 = reinterpret_cast<const float4*>(src + base)[1];
    uint4 u;
    u.x = packh2(f0.x, f0.y);
    u.y = packh2(f0.z, f0.w);
    u.z = packh2(f1.x, f1.y);
    u.w = packh2(f1.z, f1.w);
    __stcs(reinterpret_cast<uint4*>(dst + base), u);
}

// ---------------------------------------------------------------------------
// fp16 GEMM core: acc[4][4][4] = A[bm:,:] * W[bn:,:]^T (128x128x1024)
// 3-stage cp.async pipeline; tiles 128 x 64 halves, smem stride 144B. (R9)
// ---------------------------------------------------------------------------
#define GSTAGE 36864

__device__ __forceinline__ void gemm_core(const __half* __restrict__ Ab,
                                          const __half* __restrict__ Wb,
                                          uint32_t smb, float acc[4][4][4])
{
    const int tid = threadIdx.x, wid = tid >> 5, lane = tid & 31;
    const int wm = wid >> 2, wn = wid & 3;
    const int grp = lane >> 3, lr = lane & 7;
    const uint32_t arow = lr + ((grp & 1) << 3), acb = (grp & 2) << 3;
    const uint32_t brow = lr + ((grp & 2) << 2), bcb = (grp & 1) << 4;
    const int lrow = tid >> 3, lc = tid & 7;

    #pragma unroll
    for (int s = 0; s < 3; s++) {
        #pragma unroll
        for (int i = 0; i < 4; i++) {
            int row = lrow + i * 32;
            cpasync16(smb + s * GSTAGE + row * 144 + lc * 16,
                      Ab + (size_t)row * DM + s * 64 + lc * 8);
            cpasync16(smb + s * GSTAGE + 18432 + row * 144 + lc * 16,
                      Wb + (size_t)row * DM + s * 64 + lc * 8);
        }
        CP_COMMIT();
    }

    int stage = 0;
    for (int kt = 0; kt < 16; kt++) {
        CP_WAIT2();
        __syncthreads();
        const uint32_t sb = smb + stage * GSTAGE;
        #pragma unroll
        for (int kk = 0; kk < 4; kk++) {
            uint32_t af[4][4], bf[2][4];
            #pragma unroll
            for (int mf = 0; mf < 4; mf++)
                ldsm4(af[mf], sb + (wm * 64 + mf * 16 + arow) * 144 + kk * 32 + acb);
            #pragma unroll
            for (int ng = 0; ng < 2; ng++)
                ldsm4(bf[ng], sb + 18432 + (wn * 32 + ng * 16 + brow) * 144 + kk * 32 + bcb);
            #pragma unroll
            for (int mf = 0; mf < 4; mf++)
                #pragma unroll
                for (int nf = 0; nf < 4; nf++)
                    mmaf16(acc[mf][nf], af[mf], (nf & 1) ? bf[nf >> 1] + 2 : bf[nf >> 1]);
        }
        __syncthreads();
        if (kt < 13) {
            #pragma unroll
            for (int i = 0; i < 4; i++) {
                int row = lrow + i * 32;
                cpasync16(smb + stage * GSTAGE + row * 144 + lc * 16,
                          Ab + (size_t)row * DM + (kt + 3) * 64 + lc * 8);
                cpasync16(smb + stage * GSTAGE + 18432 + row * 144 + lc * 16,
                          Wb + (size_t)row * DM + (kt + 3) * 64 + lc * 8);
            }
        }
        CP_COMMIT();
        stage = (stage == 2) ? 0 : stage + 1;
    }
}

// ---------------------------------------------------------------------------
// Merged Q/K/V projections: grid (8, 64, 3). Q output pre-scaled by EXPC.
// Mode 2 additionally reduces per-column V sums into g_vsum (red-add).
// ---------------------------------------------------------------------------
__global__ void __launch_bounds__(256, 2) qkv_kernel(
    const float* __restrict__ bq, const float* __restrict__ bk,
    const float* __restrict__ bv)
{
    extern __shared__ char smc[];
    const uint32_t smb = smem_u32(smc);
    const int mode = blockIdx.z;
    const __half* A = (mode == 0) ? g_qc : (mode == 1) ? g_kc : g_vc;
    const __half* W = (mode == 0) ? g_Wqh : (mode == 1) ? g_Wkh : g_Wvh;
    const float* bias = (mode == 0) ? bq : (mode == 1) ? bk : bv;
    const int bn = blockIdx.x * 128, bm = blockIdx.y * 128;

    float acc[4][4][4] = {};
    gemm_core(A + (size_t)bm * DM, W + (size_t)bn * DM, smb, acc);

    const int tid = threadIdx.x, wid = tid >> 5, lane = tid & 31;
    const int g = lane >> 2, t = lane & 3;
    const int wm = wid >> 2, wn = wid & 3;
    const int m0 = bm + wm * 64, n0 = bn + wn * 32;
    const float osc = (mode == 0) ? EXPC : 1.f;
    float vs0[4] = {}, vs1[4] = {};
    #pragma unroll
    for (int mf = 0; mf < 4; mf++) {
        int r0 = m0 + mf * 16 + g;
        #pragma unroll
        for (int nf = 0; nf < 4; nf++) {
            int c = n0 + nf * 8 + 2 * t;
            float b0 = bias[c], b1 = bias[c + 1];
            int h = c >> 6, d = c & 63;
            #pragma unroll
            for (int half = 0; half < 2; half++) {
                int r = r0 + half * 8;
                int n = r >> 10, s = r & 1023;
                float v0 = (acc[mf][nf][half * 2 + 0] + b0) * osc;
                float v1 = (acc[mf][nf][half * 2 + 1] + b1) * osc;
                if (mode == 2) {
                    __half hv0 = __float2half_rn(v0);
                    __half hv1 = __float2half_rn(v1);
                    __half* dst = g_vTh + ((size_t)(n * HH + h) * DH + d) * SS + s;
                    dst[0] = hv0;
                    dst[SS] = hv1;
                    vs0[nf] += __half2float(hv0);
                    vs1[nf] += __half2float(hv1);
                } else {
                    __half* dst = ((mode == 0) ? g_qh : g_kh) +
                                  ((size_t)(n * HH + h) * SS + s) * DH + d;
                    *reinterpret_cast<__half2*>(dst) = __floats2half2_rn(v0, v1);
                }
            }
        }
    }
    if (mode == 2) {
        const int n = bm >> 10;
        #pragma unroll
        for (int nf = 0; nf < 4; nf++) {
            int c = n0 + nf * 8 + 2 * t;
            int h = c >> 6, d = c & 63;
            atomicAdd(&g_vsum[(n * HH + h) * DH + d], vs0[nf]);
            atomicAdd(&g_vsum[(n * HH + h) * DH + d + 1], vs1[nf]);
        }
    }
}

// ---------------------------------------------------------------------------
// Output projection: xout = g_xhh * Wo^T + bo (f32 out, streaming stores)
// ---------------------------------------------------------------------------
__global__ void __launch_bounds__(256, 2) out_kernel(
    const float* __restrict__ bo, float* __restrict__ out)
{
    extern __shared__ char smc[];
    const uint32_t smb = smem_u32(smc);
    const int bn = blockIdx.x * 128, bm = blockIdx.y * 128;

    float acc[4][4][4] = {};
    gemm_core(g_xhh + (size_t)bm * DM, g_Woh + (size_t)bn * DM, smb, acc);

    const int tid = threadIdx.x, wid = tid >> 5, lane = tid & 31;
    const int g = lane >> 2, t = lane & 3;
    const int wm = wid >> 2, wn = wid & 3;
    const int m0 = bm + wm * 64, n0 = bn + wn * 32;
    #pragma unroll
    for (int mf = 0; mf < 4; mf++) {
        int r0 = m0 + mf * 16 + g;
        #pragma unroll
        for (int nf = 0; nf < 4; nf++) {
            int c = n0 + nf * 8 + 2 * t;
            float b0 = bo[c], b1 = bo[c + 1];
            #pragma unroll
            for (int half = 0; half < 2; half++) {
                int r = r0 + half * 8;
                __stcs(reinterpret_cast<float2*>(out + (size_t)r * DM + c),
                       make_float2(acc[mf][nf][half * 2 + 0] + b0,
                                   acc[mf][nf][half * 2 + 1] + b1));
            }
        }
    }
}

// ---------------------------------------------------------------------------
// Fused attention (R11 proven-best). Q pre-scaled by EXPC.
// smem: Q 0..18432, K0 18432.., K1 36864.., V0 55296.., V1 72704..,
//       s_s @90112 (512B), pm @90624 (4KB). total 94720.
// ---------------------------------------------------------------------------
#define AQ 0u
#define AK0 18432u
#define AK1 36864u
#define AV0 55296u
#define AV1 72704u

template<bool DIAG>
__device__ __forceinline__ void p1_tile(
    uint32_t kbase, const uint32_t (&qf)[4][4], const float2* __restrict__ pm2,
    int ktbase, int gq0, int gq1, uint32_t brow, uint32_t bcb, int t,
    float& ts0, float& ts1)
{
    #pragma unroll
    for (int hh = 0; hh < 2; hh++) {
        float acc[8][4] = {};
        #pragma unroll
        for (int kk = 0; kk < 4; kk++) {
            #pragma unroll
            for (int ng = 0; ng < 4; ng++) {
                uint32_t bf[4];
                ldsm4(bf, kbase + (hh * 64 + ng * 16 + brow) * 144 + kk * 32 + bcb);
                mmaf16(acc[ng * 2], qf[kk], bf);
                mmaf16(acc[ng * 2 + 1], qf[kk], bf + 2);
            }
        }
        #pragma unroll
        for (int nf = 0; nf < 8; nf++) {
            int gk = ktbase + hh * 64 + nf * 8 + 2 * t;
            float2 pmv = pm2[gk >> 1];
            float px0 = pmv.x, py0 = pmv.y, px1 = pmv.x, py1 = pmv.y;
            if (DIAG) {
                if (gk > gq0) px0 = 0.f;
                if (gk + 1 > gq0) py0 = 0.f;
                if (gk > gq1) px1 = 0.f;
                if (gk + 1 > gq1) py1 = 0.f;
            }
            ts0 = fmaf(fexp2(acc[nf][0]), px0, ts0);
            ts0 = fmaf(fexp2(acc[nf][1]), py0, ts0);
            ts1 = fmaf(fexp2(acc[nf][2]), px1, ts1);
            ts1 = fmaf(fexp2(acc[nf][3]), py1, ts1);
        }
    }
}

template<bool DIAG>
__device__ __forceinline__ void p2_tile(
    uint32_t kbase, uint32_t vbase, const uint32_t (&qf)[4][4],
    const float2* __restrict__ pm2, int ktbase, int gq0, int gq1,
    uint32_t brow, uint32_t bcb, int t,
    float sc0, float sc1, float ad0, float ad1,
    float* __restrict__ wrow0, float* __restrict__ wrow1, float O[8][4])
{
    #pragma unroll
    for (int hh = 0; hh < 2; hh++) {
        float acc[8][4] = {};
        #pragma unroll
        for (int kk = 0; kk < 4; kk++) {
            #pragma unroll
            for (int ng = 0; ng < 4; ng++) {
                uint32_t bf[4];
                ldsm4(bf, kbase + (hh * 64 + ng * 16 + brow) * 144 + kk * 32 + bcb);
                mmaf16(acc[ng * 2], qf[kk], bf);
                mmaf16(acc[ng * 2 + 1], qf[kk], bf + 2);
            }
        }
        #pragma unroll
        for (int nfp = 0; nfp < 4; nfp++) {
            uint32_t pa[4];
            #pragma unroll
            for (int e = 0; e < 2; e++) {
                int nf = nfp * 2 + e;
                int gk = ktbase + hh * 64 + nf * 8 + 2 * t;
                float2 pmv = pm2[gk >> 1];
                float e0 = fexp2(acc[nf][0]) * pmv.x;
                float e1 = fexp2(acc[nf][1]) * pmv.y;
                float e2 = fexp2(acc[nf][2]) * pmv.x;
                float e3 = fexp2(acc[nf][3]) * pmv.y;
                if (DIAG) {
                    if (gk > gq0) e0 = 0.f;
                    if (gk + 1 > gq0) e1 = 0.f;
                    if (gk > gq1) e2 = 0.f;
                    if (gk + 1 > gq1) e3 = 0.f;
                }
                float p0 = e0 * sc0 + ad0, p1 = e1 * sc0 + ad0;
                float p2 = e2 * sc1 + ad1, p3 = e3 * sc1 + ad1;
                __stcs(reinterpret_cast<float2*>(wrow0 + gk), make_float2(p0, p1));
                __stcs(reinterpret_cast<float2*>(wrow1 + gk), make_float2(p2, p3));
                pa[e * 2 + 0] = packh2(p0, p1);
                pa[e * 2 + 1] = packh2(p2, p3);
            }
            #pragma unroll
            for (int dng = 0; dng < 4; dng++) {
                uint32_t bf[4];
                ldsm4(bf, vbase + (dng * 16 + brow) * 272 + hh * 128 + nfp * 32 + bcb);
                mmaf16(O[dng * 2], pa, bf);
                mmaf16(O[dng * 2 + 1], pa, bf + 2);
            }
        }
    }
}

__global__ void __launch_bounds__(256, 2) attn_kernel(const int* __restrict__ pad,
                                                      float* __restrict__ wout)
{
    extern __shared__ char smc[];
    const uint32_t smb = smem_u32(smc);
    float* s_s = reinterpret_cast<float*>(smc + 90112);
    float* pm = reinterpret_cast<float*>(smc + 90624);
    const float2* pm2 = reinterpret_cast<const float2*>(pm);

    const int tid = threadIdx.x, wid = tid >> 5, lane = tid & 31;
    const int g = lane >> 2, t = lane & 3;
    const int grp = lane >> 3, lr = lane & 7;
    const uint32_t arow = lr + ((grp & 1) << 3), acb = (grp & 2) << 3;
    const uint32_t brow = lr + ((grp & 2) << 2), bcb = (grp & 1) << 4;
    const int nh = blockIdx.x, n = nh >> 4, h = nh & 15;
    const int qt = 7 - blockIdx.y;
    const int q0 = qt * 128;
    const int lrow = tid >> 3, lc = tid & 7;
    const int vrow = tid >> 4, vc = tid & 15;

    const __half* qb = g_qh + ((size_t)nh * SS + q0) * DH;
    const __half* kb = g_kh + (size_t)nh * SS * DH;
    const __half* vb = g_vTh + (size_t)nh * DH * SS;

    for (int i = tid; i < SS; i += 256) pm[i] = pad[n * SS + i] ? 0.f : 1.f;

    #pragma unroll
    for (int i = 0; i < 4; i++) {
        int row = lrow + i * 32;
        cpasync16(smb + AQ + row * 144 + lc * 16, qb + (size_t)row * DH + lc * 8);
        cpasync16(smb + AK0 + row * 144 + lc * 16, kb + (size_t)row * DH + lc * 8);
    }
    CP_COMMIT();

    const int gq0 = q0 + wid * 16 + g;
    const int gq1 = gq0 + 8;
    uint32_t qf[4][4];
    float ts0 = 0.f, ts1 = 0.f;

    // ---------------- phase 1 ----------------
    for (int kt = 0; kt <= qt; kt++) {
        __syncthreads();
        if (kt < qt) {
            uint32_t kd = smb + (((kt + 1) & 1) ? AK1 : AK0);
            #pragma unroll
            for (int i = 0; i < 4; i++) {
                int row = lrow + i * 32;
                cpasync16(kd + row * 144 + lc * 16,
                          kb + (size_t)((kt + 1) * 128 + row) * DH + lc * 8);
            }
        }
        CP_COMMIT();
        CP_WAIT1();
        __syncthreads();
        if (kt == 0) {
            #pragma unroll
            for (int kk = 0; kk < 4; kk++)
                ldsm4(qf[kk], smb + AQ + (wid * 16 + arow) * 144 + kk * 32 + acb);
        }
        uint32_t kbase = smb + ((kt & 1) ? AK1 : AK0);
        if (kt < qt)
            p1_tile<false>(kbase, qf, pm2, kt * 128, gq0, gq1, brow, bcb, t, ts0, ts1);
        else
            p1_tile<true>(kbase, qf, pm2, kt * 128, gq0, gq1, brow, bcb, t, ts0, ts1);
    }

    float s0 = ts0, s1 = ts1;
    s0 += __shfl_xor_sync(0xffffffffu, s0, 1);
    s0 += __shfl_xor_sync(0xffffffffu, s0, 2);
    s1 += __shfl_xor_sync(0xffffffffu, s1, 1);
    s1 += __shfl_xor_sync(0xffffffffu, s1, 2);

    const bool d0 = (s0 == 0.f), d1 = (s1 == 0.f);
    const float inv1024 = 1.f / 1024.f;
    const float sc0 = d0 ? 0.f : 1.f / s0;
    const float sc1 = d1 ? 0.f : 1.f / s1;
    const float ad0 = d0 ? inv1024 : 0.f;
    const float ad1 = d1 ? inv1024 : 0.f;
    if (t == 0) { s_s[wid * 16 + g] = s0; s_s[wid * 16 + g + 8] = s1; }
    __syncthreads();

    // phase-2 prologue: K0 + V0 (overlaps the w-fill below)
    #pragma unroll
    for (int i = 0; i < 4; i++) {
        int row = lrow + i * 32;
        cpasync16(smb + AK0 + row * 144 + lc * 16, kb + (size_t)row * DH + lc * 8);
    }
    #pragma unroll
    for (int i = 0; i < 4; i++) {
        int row = vrow + i * 16;
        cpasync16(smb + AV0 + row * 272 + vc * 16, vb + (size_t)row * SS + vc * 8);
    }
    CP_COMMIT();

    // fill non-causal region of w
    const int fs = (qt + 1) * 128;
    if (fs < SS) {
        for (int r = 0; r < 16; r++) {
            int row = wid * 16 + r;
            float val = (s_s[row] == 0.f) ? inv1024 : 0.f;
            float4 f4 = make_float4(val, val, val, val);
            float* wr = wout + ((size_t)nh * SS + q0 + row) * SS;
            for (int c = fs + lane * 4; c < SS; c += 128)
                __stcs(reinterpret_cast<float4*>(wr + c), f4);
        }
    }

    float O[8][4] = {};
    float* wrow0 = wout + ((size_t)nh * SS + gq0) * SS;
    float* wrow1 = wout + ((size_t)nh * SS + gq1) * SS;

    // ---------------- phase 2 ----------------
    for (int kt = 0; kt <= qt; kt++) {
        __syncthreads();
        if (kt < qt) {
            uint32_t kd = smb + (((kt + 1) & 1) ? AK1 : AK0);
            uint32_t vd = smb + (((kt + 1) & 1) ? AV1 : AV0);
            #pragma unroll
            for (int i = 0; i < 4; i++) {
                int row = lrow + i * 32;
                cpasync16(kd + row * 144 + lc * 16,
                          kb + (size_t)((kt + 1) * 128 + row) * DH + lc * 8);
            }
            #pragma unroll
            for (int i = 0; i < 4; i++) {
                int row = vrow + i * 16;
                cpasync16(vd + row * 272 + vc * 16,
                          vb + (size_t)row * SS + (kt + 1) * 128 + vc * 8);
            }
        }
        CP_COMMIT();
        CP_WAIT1();
        __syncthreads();
        uint32_t kbase = smb + ((kt & 1) ? AK1 : AK0);
        uint32_t vbase = smb + ((kt & 1) ? AV1 : AV0);
        if (kt < qt)
            p2_tile<false>(kbase, vbase, qf, pm2, kt * 128, gq0, gq1, brow, bcb, t,
                           sc0, sc1, ad0, ad1, wrow0, wrow1, O);
        else
            p2_tile<true>(kbase, vbase, qf, pm2, kt * 128, gq0, gq1, brow, bcb, t,
                          sc0, sc1, ad0, ad1, wrow0, wrow1, O);
    }

    // ---------------- epilogue: write O (fp16) ----------------
    #pragma unroll
    for (int dn = 0; dn < 8; dn++) {
        int d = dn * 8 + 2 * t;
        float o0 = O[dn][0], o1 = O[dn][1], o2 = O[dn][2], o3 = O[dn][3];
        if (d0) {
            o0 = g_vsum[nh * DH + d] * inv1024;
            o1 = g_vsum[nh * DH + d + 1] * inv1024;
        }
        if (d1) {
            o2 = g_vsum[nh * DH + d] * inv1024;
            o3 = g_vsum[nh * DH + d + 1] * inv1024;
        }
        *reinterpret_cast<__half2*>(
            g_xhh + ((size_t)(n * SS + gq0) * HH + h) * DH + d) = __floats2half2_rn(o0, o1);
        *reinterpret_cast<__half2*>(
            g_xhh + ((size_t)(n * SS + gq1) * HH + h) * DH + d) = __floats2half2_rn(o2, o3);
    }
}

// ---------------------------------------------------------------------------
extern "C" void kernel_launch(void* const* d_in, const int* in_sizes, int n_in,
                              void* d_out, int out_size)
{
    const float* q   = (const float*)d_in[0];
    const float* k   = (const float*)d_in[1];
    const float* v   = (const float*)d_in[2];
    // d_in[3] = causal_mask (computed analytically)
    const int*   pad = (const int*)d_in[4];
    const float* Wq  = (const float*)d_in[5];
    const float* bq  = (const float*)d_in[6];
    const float* Wk  = (const float*)d_in[7];
    const float* bk  = (const float*)d_in[8];
    const float* Wv  = (const float*)d_in[9];
    const float* bv  = (const float*)d_in[10];
    const float* Wo  = (const float*)d_in[11];
    const float* bo  = (const float*)d_in[12];

    float* xout = (float*)d_out;                        // [8,1024,1024]
    float* wout = (float*)d_out + (size_t)NB * SS * DM; // [8,16,1024,1024]

    const int GEMM_SMEM = 3 * GSTAGE;   // 110592
    const int ATTN_SMEM = 94720;
    cudaFuncSetAttribute(qkv_kernel, cudaFuncAttributeMaxDynamicSharedMemorySize, GEMM_SMEM);
    cudaFuncSetAttribute(out_kernel, cudaFuncAttributeMaxDynamicSharedMemorySize, GEMM_SMEM);
    cudaFuncSetAttribute(attn_kernel, cudaFuncAttributeMaxDynamicSharedMemorySize, ATTN_SMEM);

    dim3 cg(4096, 1, 7);
    cvt_kernel<<<cg, 256>>>(q, k, v, Wq, Wk, Wv, Wo);

    dim3 qkvg(DM / 128, (NB * SS) / 128, 3);   // (8, 64, 3)
    qkv_kernel<<<qkvg, 256, GEMM_SMEM>>>(bq, bk, bv);

    dim3 ag(NB * HH, 8);                       // (128 nh, 8 q-tiles)
    attn_kernel<<<ag, 256, ATTN_SMEM>>>(pad, wout);

    dim3 og(DM / 128, (NB * SS) / 128);        // (8, 64)
    out_kernel<<<og, 256, GEMM_SMEM>>>(bo, xout);
}